// round 9
// baseline (speedup 1.0000x reference)
#include <cuda_runtime.h>
#include <math.h>

#define B_    2
#define L_    4096
#define K_    32
#define HALF_ 128
#define NPAIR 28
#define EPSF  1e-6f
#define TWOPI 6.28318530717958647692f
#define BL_   (B_*L_)
#define GRID_ 456

typedef unsigned long long ull;
typedef long long ll;

__device__ float g_wsym[NPAIR*HALF_];   // 2pi*(W[mn]+W[nm])
__device__ float g_wv[3*HALF_];         // 2pi*W_vec
__device__ float g_bias[HALF_];         // 2pi*sqrt(EPS)*sum_diag W

__constant__ int c_pm[NPAIR] = {0,0,0,0,0,0,0,1,1,1,1,1,1,2,2,2,2,2,3,3,3,3,4,4,4,5,5,6};
__constant__ int c_pn[NPAIR] = {1,2,3,4,5,6,7,2,3,4,5,6,7,3,4,5,6,7,4,5,6,7,5,6,7,6,7,7};

static __device__ __forceinline__ ull pack2(float lo, float hi){
    ull r; asm("mov.b64 %0, {%1,%2};" : "=l"(r) : "f"(lo), "f"(hi)); return r;
}
static __device__ __forceinline__ void unpack2(ull v, float& lo, float& hi){
    asm("mov.b64 {%0,%1}, %2;" : "=f"(lo), "=f"(hi) : "l"(v));
}
static __device__ __forceinline__ ull fma2(ull a, ull b, ull c){
    ull d; asm("fma.rn.f32x2 %0, %1, %2, %3;" : "=l"(d) : "l"(a), "l"(b), "l"(c)); return d;
}
static __device__ __forceinline__ ull mul2(ull a, ull b){
    ull d; asm("mul.rn.f32x2 %0, %1, %2;" : "=l"(d) : "l"(a), "l"(b)); return d;
}
static __device__ __forceinline__ ull dup2(float x){ return pack2(x, x); }

// ---------------------------------------------------------------------------
__global__ void wprep_kernel(const float* __restrict__ Wvec, const float* __restrict__ Wdist){
    int e = threadIdx.x;  // 0..127
    #pragma unroll
    for (int d = 0; d < 3; d++) g_wv[d*HALF_ + e] = TWOPI * Wvec[d*HALF_ + e];
    float b = 0.f;
    #pragma unroll
    for (int m = 0; m < 8; m++) b += Wdist[(m*8+m)*HALF_ + e];
    g_bias[e] = TWOPI * sqrtf(EPSF) * b;
    for (int p = 0; p < NPAIR; p++){
        int m = c_pm[p], n = c_pn[p];
        g_wsym[p*HALF_ + e] = TWOPI * (Wdist[(m*8+n)*HALF_ + e] + Wdist[(n*8+m)*HALF_ + e]);
    }
}

// ---------------------------------------------------------------------------
static __device__ __forceinline__ void make_frame(
    float Nx, float Ny, float Nz, float Ax, float Ay, float Az,
    float Cx, float Cy, float Cz, float mask, float* dst)
{
    float v1x=Nx-Ax, v1y=Ny-Ay, v1z=Nz-Az;
    float n1 = sqrtf(v1x*v1x + v1y*v1y + v1z*v1z) + EPSF;
    float e1x=v1x/n1, e1y=v1y/n1, e1z=v1z/n1;

    float u2x=Cx-Ax, u2y=Cy-Ay, u2z=Cz-Az;
    float n2 = sqrtf(u2x*u2x + u2y*u2y + u2z*u2z) + EPSF;
    u2x/=n2; u2y/=n2; u2z/=n2;

    float dt = u2x*e1x + u2y*e1y + u2z*e1z;
    float w2x = u2x - dt*e1x, w2y = u2y - dt*e1y, w2z = u2z - dt*e1z;
    float n3 = sqrtf(w2x*w2x + w2y*w2y + w2z*w2z) + EPSF;
    float e2x=w2x/n3, e2y=w2y/n3, e2z=w2z/n3;

    float e3x = e1y*e2z - e1z*e2y;
    float e3y = e1z*e2x - e1x*e2z;
    float e3z = e1x*e2y - e1y*e2x;

    dst[0]=mask*e1x; dst[1]=mask*e1y; dst[2]=mask*e1z;
    dst[3]=mask*e2x; dst[4]=mask*e2y; dst[5]=mask*e2z;
    dst[6]=mask*e3x; dst[7]=mask*e3y; dst[8]=mask*e3z;
    dst[9]=mask*Ax;  dst[10]=mask*Ay; dst[11]=mask*Az;
}

// ---------------------------------------------------------------------------
// Persistent kernel (R7 structure). s_d and s_t store PRE-DUPLICATED values
// so hd-loop / epilogue packed operands come straight from vector LDS with
// zero register-duplication MOVs.
// ---------------------------------------------------------------------------
__global__ __launch_bounds__(256, 3)
void edge_kernel(const float* __restrict__ X, const void* __restrict__ eidxv,
                 const void* __restrict__ Cv, float* __restrict__ out){
    __shared__ __align__(16) float s_wsym[NPAIR*HALF_];  // 14336 B
    __shared__ __align__(16) float s_wv[3*HALF_];        // 1536 B
    __shared__ __align__(16) float s_bias[HALF_];        // 512 B
    __shared__ __align__(16) float s_fr[12];
    __shared__ __align__(16) float s_xi[12];
    __shared__ __align__(16) float s_xj[K_*12];          // 1536 B
    __shared__             float s_mj[K_];
    __shared__ __align__(16) float s_d[K_*NPAIR*2];      // 7168 B, {d,d} pairs
    __shared__ __align__(16) float s_t[K_*8];            // 1024 B, {t0,t0,t1,t1,t2,t2,0,0}

    int tid  = threadIdx.x;
    int w    = tid >> 5, lane = tid & 31;

    // --- per-warp dtype detection (int64 => odd 32-bit words all zero) ---
    int4 ve = ((const int4*)eidxv)[lane];
    int4 vc = ((const int4*)Cv)[lane];
    int is64  = (__reduce_or_sync(0xffffffffu, ve.y | ve.w) == 0);
    int is64C = (__reduce_or_sync(0xffffffffu, vc.y | vc.w) == 0);

    // --- W staging: ONCE per block ---
    {
        const float4* src = (const float4*)g_wsym;
        float4* dst = (float4*)s_wsym;
        #pragma unroll
        for (int i = tid; i < NPAIR*HALF_/4; i += 256) dst[i] = src[i];
    }
    if (tid < 96)                ((float4*)s_wv)[tid]      = ((const float4*)g_wv)[tid];
    if (tid >= 96 && tid < 128)  ((float4*)s_bias)[tid-96] = ((const float4*)g_bias)[tid-96];

    // role constants
    int kk_x = 0, part_x = 0;
    if (tid < 96){ kk_x = tid/3; part_x = tid - kk_x*3; }
    int kk_m = tid - 224;

    // --- prologue: stage residue r0 synchronously ---
    int r = blockIdx.x;
    {
        int bbase = r & ~(L_-1);
        if (tid < 96){
            ll j = is64 ? ((const ll*)eidxv)[r*K_ + kk_x]
                        : (ll)((const int*)eidxv)[r*K_ + kk_x];
            ((float4*)&s_xj[kk_x*12])[part_x] = ((const float4*)X)[(bbase+(int)j)*3 + part_x];
        } else if (tid < 99){
            ((float4*)s_xi)[tid-96] = ((const float4*)X)[r*3 + (tid-96)];
        } else if (tid == 99){
            const float* x = X + (size_t)r * 12;
            ll cv = is64C ? ((const ll*)Cv)[r] : (ll)((const int*)Cv)[r];
            make_frame(x[0],x[1],x[2], x[3],x[4],x[5], x[6],x[7],x[8],
                       (cv > 0) ? 1.f : 0.f, s_fr);
        } else if (tid >= 224){
            ll j = is64 ? ((const ll*)eidxv)[r*K_ + kk_m]
                        : (ll)((const int*)eidxv)[r*K_ + kk_m];
            int jg = bbase + (int)j;
            ll cval = is64C ? ((const ll*)Cv)[jg] : (ll)((const int*)Cv)[jg];
            s_mj[kk_m] = (cval > 0) ? 1.f : 0.f;
        }
    }
    // preload idx for r + GRID_ (stage-1 of pipeline)
    ll jj = 0;
    if (r + GRID_ < BL_){
        if (tid < 96)        jj = is64 ? ((const ll*)eidxv)[(r+GRID_)*K_ + kk_x]
                                       : (ll)((const int*)eidxv)[(r+GRID_)*K_ + kk_x];
        else if (tid >= 224) jj = is64 ? ((const ll*)eidxv)[(r+GRID_)*K_ + kk_m]
                                       : (ll)((const int*)eidxv)[(r+GRID_)*K_ + kk_m];
    }
    __syncthreads();

    while (true){
        int rn = r + GRID_;
        bool hn = rn < BL_;

        // --- issue prefetch loads for rn into registers ---
        float4 na = make_float4(0.f,0.f,0.f,0.f);
        ll ncv = 1;
        ll jj2 = 0;
        if (hn){
            int bb = rn & ~(L_-1);
            if (tid < 96)        na = ((const float4*)X)[(bb+(int)jj)*3 + part_x];
            else if (tid < 99)   na = ((const float4*)X)[rn*3 + (tid-96)];
            else if (tid == 99)  ncv = is64C ? ((const ll*)Cv)[rn] : (ll)((const int*)Cv)[rn];
            else if (tid >= 224) ncv = is64C ? ((const ll*)Cv)[bb+(int)jj]
                                             : (ll)((const int*)Cv)[bb+(int)jj];
            int r2 = rn + GRID_;
            if (r2 < BL_){
                if (tid < 96)        jj2 = is64 ? ((const ll*)eidxv)[r2*K_ + kk_x]
                                                : (ll)((const int*)eidxv)[r2*K_ + kk_x];
                else if (tid >= 224) jj2 = is64 ? ((const ll*)eidxv)[r2*K_ + kk_m]
                                                : (ll)((const int*)eidxv)[r2*K_ + kk_m];
            }
        }

        // --- distance + t_ji phase: warp w -> edges w*4..w*4+3 ---
        if (lane < NPAIR){
            int m = c_pm[lane], n = c_pn[lane];
            bool mI = (m < 4), nI = (n < 4);
            float mx=0.f,my=0.f,mz=0.f, nx=0.f,ny=0.f,nz=0.f;
            if (mI){ mx=s_xi[m*3]; my=s_xi[m*3+1]; mz=s_xi[m*3+2]; }
            if (nI){ nx=s_xi[n*3]; ny=s_xi[n*3+1]; nz=s_xi[n*3+2]; }
            #pragma unroll
            for (int e = 0; e < 4; e++){
                int k = w*4 + e;
                const float* xj = &s_xj[k*12];
                float ax = mI ? mx : xj[(m-4)*3+0];
                float ay = mI ? my : xj[(m-4)*3+1];
                float az = mI ? mz : xj[(m-4)*3+2];
                float bx = nI ? nx : xj[(n-4)*3+0];
                float by = nI ? ny : xj[(n-4)*3+1];
                float bz = nI ? nz : xj[(n-4)*3+2];
                float dx=ax-bx, dy=ay-by, dz=az-bz;
                float dd = fmaf(dx,dx, fmaf(dy,dy, fmaf(dz,dz, EPSF)));
                float dist = __fsqrt_rn(dd);
                ((float2*)s_d)[k*NPAIR + lane] = make_float2(dist, dist);
            }
        } else {
            int k = w*4 + (lane - NPAIR);
            float e1x=s_fr[0], e1y=s_fr[1], e1z=s_fr[2];
            float e2x=s_fr[3], e2y=s_fr[4], e2z=s_fr[5];
            float e3x=s_fr[6], e3y=s_fr[7], e3z=s_fr[8];
            float tix=s_fr[9], tiy=s_fr[10], tiz=s_fr[11];
            float mj = s_mj[k];
            float dx = fmaf(mj, s_xj[k*12+3], -tix);
            float dy = fmaf(mj, s_xj[k*12+4], -tiy);
            float dz = fmaf(mj, s_xj[k*12+5], -tiz);
            float t0 = fmaf(e1z,dz, fmaf(e1y,dy, e1x*dx));
            float t1 = fmaf(e2z,dz, fmaf(e2y,dy, e2x*dx));
            float t2 = fmaf(e3z,dz, fmaf(e3y,dy, e3x*dx));
            ((float4*)&s_t[k*8])[0] = make_float4(t0, t0, t1, t1);
            ((float4*)&s_t[k*8])[1] = make_float4(t2, t2, 0.f, 0.f);
        }
        __syncthreads();

        // --- compute phase: warp (cg,eg): 64 cols x 8 edges ---
        {
            int cg = w >> 2;
            int eg = w & 3;
            int col = cg*64 + lane*2;
            int eb  = eg * 8;

            ull hd[8];
            {
                float2 bq = *(const float2*)&s_bias[col];
                ull b2 = pack2(bq.x, bq.y);
                #pragma unroll
                for (int e = 0; e < 8; e++) hd[e] = b2;
            }
            #pragma unroll 1
            for (int pp = 0; pp < NPAIR; pp += 4){
                float2 q0 = *(const float2*)&s_wsym[(pp+0)*HALF_ + col];
                float2 q1 = *(const float2*)&s_wsym[(pp+1)*HALF_ + col];
                float2 q2 = *(const float2*)&s_wsym[(pp+2)*HALF_ + col];
                float2 q3 = *(const float2*)&s_wsym[(pp+3)*HALF_ + col];
                ull W0 = pack2(q0.x,q0.y), W1 = pack2(q1.x,q1.y);
                ull W2 = pack2(q2.x,q2.y), W3 = pack2(q3.x,q3.y);
                #pragma unroll
                for (int e = 0; e < 8; e++){
                    // broadcast: {dp,dp,dp+1,dp+1} and {dp+2,dp+2,dp+3,dp+3}
                    float4 da = *(const float4*)&s_d[((eb+e)*NPAIR + pp)*2];
                    float4 db = *(const float4*)&s_d[((eb+e)*NPAIR + pp+2)*2];
                    hd[e] = fma2(pack2(da.x,da.y), W0, hd[e]);
                    hd[e] = fma2(pack2(da.z,da.w), W1, hd[e]);
                    hd[e] = fma2(pack2(db.x,db.y), W2, hd[e]);
                    hd[e] = fma2(pack2(db.z,db.w), W3, hd[e]);
                }
            }

            float2 wv0 = *(const float2*)&s_wv[0*HALF_ + col];
            float2 wv1 = *(const float2*)&s_wv[1*HALF_ + col];
            float2 wv2 = *(const float2*)&s_wv[2*HALF_ + col];
            ull v0 = pack2(wv0.x, wv0.y);
            ull v1 = pack2(wv1.x, wv1.y);
            ull v2 = pack2(wv2.x, wv2.y);

            #pragma unroll
            for (int e = 0; e < 8; e++){
                int k = eb + e;
                float4 ta = *(const float4*)&s_t[k*8];      // {t0,t0,t1,t1}
                float4 tb = *(const float4*)&s_t[k*8 + 4];  // {t2,t2,0,0}
                ull hv = fma2(pack2(tb.x,tb.y), v2,
                          fma2(pack2(ta.z,ta.w), v1,
                           mul2(pack2(ta.x,ta.y), v0)));

                float a0,a1,b0,b1;
                unpack2(hv, a0, a1);
                unpack2(hd[e], b0, b1);
                float sa0,ca0,sa1,ca1,sb0,cb0,sb1,cb1;
                __sincosf(a0,&sa0,&ca0); __sincosf(a1,&sa1,&ca1);
                __sincosf(b0,&sb0,&cb0); __sincosf(b1,&sb1,&cb1);
                size_t obase = ((size_t)(r*K_ + k))*256 + col;
                __stcs((float2*)&out[obase],       make_float2(ca0+cb0, ca1+cb1));
                __stcs((float2*)&out[obase + 128], make_float2(sa0+sb0, sa1+sb1));
            }
        }

        // --- store prefetched data for rn ---
        if (hn){
            if (tid < 96)           ((float4*)&s_xj[kk_x*12])[part_x] = na;
            else if (tid < 99)      ((float4*)s_xi)[tid-96] = na;
            else if (tid >= 224)    s_mj[kk_m] = (ncv > 0) ? 1.f : 0.f;
            if (w == 3){
                float q0x=__shfl_sync(0xffffffffu, na.x, 0);
                float q0y=__shfl_sync(0xffffffffu, na.y, 0);
                float q0z=__shfl_sync(0xffffffffu, na.z, 0);
                float q0w=__shfl_sync(0xffffffffu, na.w, 0);
                float q1x=__shfl_sync(0xffffffffu, na.x, 1);
                float q1y=__shfl_sync(0xffffffffu, na.y, 1);
                float q1z=__shfl_sync(0xffffffffu, na.z, 1);
                float q1w=__shfl_sync(0xffffffffu, na.w, 1);
                float q2x=__shfl_sync(0xffffffffu, na.x, 2);
                if (lane == 3){
                    make_frame(q0x,q0y,q0z, q0w,q1x,q1y, q1z,q1w,q2x,
                               (ncv > 0) ? 1.f : 0.f, s_fr);
                }
            }
        }
        __syncthreads();
        if (!hn) break;
        r = rn; jj = jj2;
    }
}

// ---------------------------------------------------------------------------
extern "C" void kernel_launch(void* const* d_in, const int* in_sizes, int n_in,
                              void* d_out, int out_size){
    const float* X     = (const float*)d_in[0];
    const void*  eidx  = d_in[1];
    const void*  C     = d_in[2];
    const float* Wvec  = (const float*)d_in[3];
    const float* Wdist = (const float*)d_in[4];
    (void)in_sizes; (void)n_in; (void)out_size;

    wprep_kernel<<<1, 128>>>(Wvec, Wdist);
    edge_kernel<<<GRID_, 256>>>(X, eidx, C, (float*)d_out);
}

// round 10
// speedup vs baseline: 1.3188x; 1.3188x over previous
#include <cuda_runtime.h>
#include <math.h>

#define B_    2
#define L_    4096
#define K_    32
#define HALF_ 128
#define NPAIR 28
#define EPSF  1e-6f
#define TWOPI 6.28318530717958647692f
#define BL_   (B_*L_)
#define GRID_ 608

typedef unsigned long long ull;
typedef long long ll;

__device__ float g_wsym[NPAIR*HALF_];   // 2pi*(W[mn]+W[nm])
__device__ float g_wv[3*HALF_];         // 2pi*W_vec
__device__ float g_bias[HALF_];         // 2pi*sqrt(EPS)*sum_diag W
__device__ float g_fr[BL_*16];          // per res: e1[0:3) e2[4:7) e3[8:11) t[12:15), masked

__constant__ int c_pm[NPAIR] = {0,0,0,0,0,0,0,1,1,1,1,1,1,2,2,2,2,2,3,3,3,3,4,4,4,5,5,6};
__constant__ int c_pn[NPAIR] = {1,2,3,4,5,6,7,2,3,4,5,6,7,3,4,5,6,7,4,5,6,7,5,6,7,6,7,7};

static __device__ __forceinline__ ull pack2(float lo, float hi){
    ull r; asm("mov.b64 %0, {%1,%2};" : "=l"(r) : "f"(lo), "f"(hi)); return r;
}
static __device__ __forceinline__ void unpack2(ull v, float& lo, float& hi){
    asm("mov.b64 {%0,%1}, %2;" : "=f"(lo), "=f"(hi) : "l"(v));
}
static __device__ __forceinline__ ull fma2(ull a, ull b, ull c){
    ull d; asm("fma.rn.f32x2 %0, %1, %2, %3;" : "=l"(d) : "l"(a), "l"(b), "l"(c)); return d;
}
static __device__ __forceinline__ ull mul2(ull a, ull b){
    ull d; asm("mul.rn.f32x2 %0, %1, %2;" : "=l"(d) : "l"(a), "l"(b)); return d;
}
static __device__ __forceinline__ ull dup2(float x){ return pack2(x, x); }

static __device__ __forceinline__ unsigned sa(const void* p){
    return (unsigned)__cvta_generic_to_shared(p);
}
static __device__ __forceinline__ void cp16(unsigned s, const void* g){
    asm volatile("cp.async.ca.shared.global [%0], [%1], 16;" :: "r"(s), "l"(g));
}
static __device__ __forceinline__ void cp8(unsigned s, const void* g){
    asm volatile("cp.async.ca.shared.global [%0], [%1], 8;" :: "r"(s), "l"(g));
}
static __device__ __forceinline__ void cp4(unsigned s, const void* g){
    asm volatile("cp.async.ca.shared.global [%0], [%1], 4;" :: "r"(s), "l"(g));
}

// ---------------------------------------------------------------------------
// Prep: block 0 = W preparation; blocks 1..32 = frames (masked R rows + t).
// ---------------------------------------------------------------------------
__global__ void prep_kernel(const float* __restrict__ X, const void* __restrict__ Cv,
                            const float* __restrict__ Wvec, const float* __restrict__ Wdist){
    if (blockIdx.x == 0){
        int e = threadIdx.x;
        if (e >= 128) return;
        #pragma unroll
        for (int d = 0; d < 3; d++) g_wv[d*HALF_ + e] = TWOPI * Wvec[d*HALF_ + e];
        float b = 0.f;
        #pragma unroll
        for (int m = 0; m < 8; m++) b += Wdist[(m*8+m)*HALF_ + e];
        g_bias[e] = TWOPI * sqrtf(EPSF) * b;
        for (int p = 0; p < NPAIR; p++){
            int m = c_pm[p], n = c_pn[p];
            g_wsym[p*HALF_ + e] = TWOPI * (Wdist[(m*8+n)*HALF_ + e] + Wdist[(n*8+m)*HALF_ + e]);
        }
        return;
    }
    int r = (blockIdx.x - 1)*256 + threadIdx.x;   // 32*256 = 8192
    // C dtype: int64 buffers have zero odd 32-bit words
    int4 vc = ((const int4*)Cv)[threadIdx.x & 31];
    int is64C = (__reduce_or_sync(0xffffffffu, vc.y | vc.w) == 0);
    ll cv = is64C ? ((const ll*)Cv)[r] : (ll)((const int*)Cv)[r];
    float mask = (cv > 0) ? 1.f : 0.f;

    const float* x = X + (size_t)r * 12;
    float Nx=x[0], Ny=x[1], Nz=x[2];
    float Ax=x[3], Ay=x[4], Az=x[5];
    float Cx=x[6], Cy=x[7], Cz=x[8];

    float v1x=Nx-Ax, v1y=Ny-Ay, v1z=Nz-Az;
    float n1 = sqrtf(v1x*v1x + v1y*v1y + v1z*v1z) + EPSF;
    float e1x=v1x/n1, e1y=v1y/n1, e1z=v1z/n1;

    float u2x=Cx-Ax, u2y=Cy-Ay, u2z=Cz-Az;
    float n2 = sqrtf(u2x*u2x + u2y*u2y + u2z*u2z) + EPSF;
    u2x/=n2; u2y/=n2; u2z/=n2;

    float dt = u2x*e1x + u2y*e1y + u2z*e1z;
    float w2x = u2x - dt*e1x, w2y = u2y - dt*e1y, w2z = u2z - dt*e1z;
    float n3 = sqrtf(w2x*w2x + w2y*w2y + w2z*w2z) + EPSF;
    float e2x=w2x/n3, e2y=w2y/n3, e2z=w2z/n3;

    float e3x = e1y*e2z - e1z*e2y;
    float e3y = e1z*e2x - e1x*e2z;
    float e3z = e1x*e2y - e1y*e2x;

    float4* g4 = (float4*)g_fr + (size_t)r*4;
    g4[0] = make_float4(mask*e1x, mask*e1y, mask*e1z, 0.f);
    g4[1] = make_float4(mask*e2x, mask*e2y, mask*e2z, 0.f);
    g4[2] = make_float4(mask*e3x, mask*e3y, mask*e3z, 0.f);
    g4[3] = make_float4(mask*Ax,  mask*Ay,  mask*Az,  0.f);
}

// ---------------------------------------------------------------------------
// Persistent main kernel: 608 blocks, 4/SM. Zero-register cp.async prefetch
// into double-buffered smem; R7 hot loop verbatim.
// ---------------------------------------------------------------------------
__global__ __launch_bounds__(256, 4)
void edge_kernel(const float* __restrict__ X, const void* __restrict__ eidxv,
                 float* __restrict__ out){
    __shared__ __align__(16) float s_wsym[NPAIR*HALF_];  // 14336 B
    __shared__ __align__(16) float s_wv[3*HALF_];        // 1536 B
    __shared__ __align__(16) float s_bias[HALF_];        // 512 B
    __shared__ __align__(16) float s_xj[2][K_*12];       // 3072 B
    __shared__ __align__(16) float s_tj[2][K_*4];        // 1024 B
    __shared__ __align__(16) float s_fri[2][16];         // 128 B
    __shared__ __align__(16) float s_xi[2][12];          // 96 B
    __shared__ __align__(16) ll    s_jb[2][K_];          // 512 B
    __shared__ __align__(16) float s_d[K_*NPAIR];        // 3584 B
    __shared__ __align__(16) float s_t[K_*4];            // 512 B

    int tid  = threadIdx.x;
    int w    = tid >> 5, lane = tid & 31;

    // eidx dtype: int64 => odd 32-bit words all zero
    int4 ve = ((const int4*)eidxv)[lane];
    int is64 = (__reduce_or_sync(0xffffffffu, ve.y | ve.w) == 0);

    // W staging once per block
    {
        const float4* src = (const float4*)g_wsym;
        float4* dst = (float4*)s_wsym;
        #pragma unroll
        for (int i = tid; i < NPAIR*HALF_/4; i += 256) dst[i] = src[i];
    }
    if (tid < 96)                ((float4*)s_wv)[tid]      = ((const float4*)g_wv)[tid];
    if (tid >= 96 && tid < 128)  ((float4*)s_bias)[tid-96] = ((const float4*)g_bias)[tid-96];

    int kk_x = 0, part_x = 0;
    if (tid < 96){ kk_x = tid/3; part_x = tid - kk_x*3; }

    // --- prologue: synchronous staging of residue r0 + jbuf for r0+GRID ---
    int r = blockIdx.x;
    {
        int bb = r & ~(L_-1);
        if (tid < 96){
            ll j = is64 ? ((const ll*)eidxv)[r*K_ + kk_x]
                        : (ll)((const int*)eidxv)[r*K_ + kk_x];
            ((float4*)&s_xj[0][kk_x*12])[part_x] = ((const float4*)X)[(bb+(int)j)*3 + part_x];
        } else if (tid < 128){
            int k = tid - 96;
            ll j = is64 ? ((const ll*)eidxv)[r*K_ + k]
                        : (ll)((const int*)eidxv)[r*K_ + k];
            ((float4*)&s_tj[0][k*4])[0] = ((const float4*)g_fr)[(size_t)(bb+(int)j)*4 + 3];
        } else if (tid < 132){
            ((float4*)s_fri[0])[tid-128] = ((const float4*)g_fr)[(size_t)r*4 + (tid-128)];
        } else if (tid < 135){
            ((float4*)s_xi[0])[tid-132] = ((const float4*)X)[r*3 + (tid-132)];
        } else if (tid >= 136 && tid < 168 && r + GRID_ < BL_){
            int k = tid - 136;
            s_jb[0][k] = is64 ? ((const ll*)eidxv)[(r+GRID_)*K_ + k]
                              : (ll)((const int*)eidxv)[(r+GRID_)*K_ + k];
        }
    }
    __syncthreads();

    int b = 0;
    while (true){
        int rn = r + GRID_;
        bool hn = rn < BL_;

        // --- zero-register prefetch for rn via cp.async ---
        if (hn){
            int bb = rn & ~(L_-1);
            if (tid < 96){
                ll j = is64 ? s_jb[b][kk_x] : (ll)(*(const int*)&s_jb[b][kk_x]);
                cp16(sa(&s_xj[b^1][kk_x*12 + part_x*4]),
                     (const char*)X + ((size_t)(bb+(int)j)*12 + part_x*4)*4);
            } else if (tid < 128){
                int k = tid - 96;
                ll j = is64 ? s_jb[b][k] : (ll)(*(const int*)&s_jb[b][k]);
                cp16(sa(&s_tj[b^1][k*4]),
                     (const char*)g_fr + ((size_t)(bb+(int)j)*16 + 12)*4);
            } else if (tid < 132){
                cp16(sa(&s_fri[b^1][(tid-128)*4]),
                     (const char*)g_fr + ((size_t)rn*16 + (tid-128)*4)*4);
            } else if (tid < 135){
                cp16(sa(&s_xi[b^1][(tid-132)*4]),
                     (const char*)X + ((size_t)rn*12 + (tid-132)*4)*4);
            } else if (tid >= 136 && tid < 168 && rn + GRID_ < BL_){
                int k = tid - 136;
                if (is64) cp8(sa(&s_jb[b^1][k]),
                              (const char*)eidxv + ((size_t)(rn+GRID_)*K_ + k)*8);
                else      cp4(sa(&s_jb[b^1][k]),
                              (const char*)eidxv + ((size_t)(rn+GRID_)*K_ + k)*4);
            }
            asm volatile("cp.async.commit_group;" ::: "memory");
        }

        // --- distance + t_ji phase: warp w -> edges w*4..w*4+3 ---
        if (lane < NPAIR){
            int m = c_pm[lane], n = c_pn[lane];
            bool mI = (m < 4), nI = (n < 4);
            float mx=0.f,my=0.f,mz=0.f, nx=0.f,ny=0.f,nz=0.f;
            if (mI){ mx=s_xi[b][m*3]; my=s_xi[b][m*3+1]; mz=s_xi[b][m*3+2]; }
            if (nI){ nx=s_xi[b][n*3]; ny=s_xi[b][n*3+1]; nz=s_xi[b][n*3+2]; }
            #pragma unroll
            for (int e = 0; e < 4; e++){
                int k = w*4 + e;
                const float* xj = &s_xj[b][k*12];
                float ax = mI ? mx : xj[(m-4)*3+0];
                float ay = mI ? my : xj[(m-4)*3+1];
                float az = mI ? mz : xj[(m-4)*3+2];
                float bx = nI ? nx : xj[(n-4)*3+0];
                float by = nI ? ny : xj[(n-4)*3+1];
                float bz = nI ? nz : xj[(n-4)*3+2];
                float dx=ax-bx, dy=ay-by, dz=az-bz;
                float dd = fmaf(dx,dx, fmaf(dy,dy, fmaf(dz,dz, EPSF)));
                s_d[k*NPAIR + lane] = __fsqrt_rn(dd);
            }
        } else {
            int k = w*4 + (lane - NPAIR);
            float4 f0 = ((const float4*)s_fri[b])[0];   // e1
            float4 f1 = ((const float4*)s_fri[b])[1];   // e2
            float4 f2 = ((const float4*)s_fri[b])[2];   // e3
            float4 f3 = ((const float4*)s_fri[b])[3];   // t_i
            float4 tj = ((const float4*)&s_tj[b][k*4])[0];
            float dx = tj.x - f3.x, dy = tj.y - f3.y, dz = tj.z - f3.z;
            float t0 = fmaf(f0.z,dz, fmaf(f0.y,dy, f0.x*dx));
            float t1 = fmaf(f1.z,dz, fmaf(f1.y,dy, f1.x*dx));
            float t2 = fmaf(f2.z,dz, fmaf(f2.y,dy, f2.x*dx));
            ((float4*)&s_t[k*4])[0] = make_float4(t0, t1, t2, 0.f);
        }
        __syncthreads();

        // --- compute phase: warp (cg,eg): 64 cols x 8 edges (R7 hot loop) ---
        {
            int cg = w >> 2;
            int eg = w & 3;
            int col = cg*64 + lane*2;
            int eb  = eg * 8;

            ull hd[8];
            {
                float2 bq = *(const float2*)&s_bias[col];
                ull b2 = pack2(bq.x, bq.y);
                #pragma unroll
                for (int e = 0; e < 8; e++) hd[e] = b2;
            }
            #pragma unroll 1
            for (int pp = 0; pp < NPAIR; pp += 4){
                float2 q0 = *(const float2*)&s_wsym[(pp+0)*HALF_ + col];
                float2 q1 = *(const float2*)&s_wsym[(pp+1)*HALF_ + col];
                float2 q2 = *(const float2*)&s_wsym[(pp+2)*HALF_ + col];
                float2 q3 = *(const float2*)&s_wsym[(pp+3)*HALF_ + col];
                ull W0 = pack2(q0.x,q0.y), W1 = pack2(q1.x,q1.y);
                ull W2 = pack2(q2.x,q2.y), W3 = pack2(q3.x,q3.y);
                #pragma unroll
                for (int e = 0; e < 8; e++){
                    float4 dq = *(const float4*)&s_d[(eb+e)*NPAIR + pp];  // broadcast
                    hd[e] = fma2(dup2(dq.x), W0, hd[e]);
                    hd[e] = fma2(dup2(dq.y), W1, hd[e]);
                    hd[e] = fma2(dup2(dq.z), W2, hd[e]);
                    hd[e] = fma2(dup2(dq.w), W3, hd[e]);
                }
            }

            float2 wv0 = *(const float2*)&s_wv[0*HALF_ + col];
            float2 wv1 = *(const float2*)&s_wv[1*HALF_ + col];
            float2 wv2 = *(const float2*)&s_wv[2*HALF_ + col];
            ull v0 = pack2(wv0.x, wv0.y);
            ull v1 = pack2(wv1.x, wv1.y);
            ull v2 = pack2(wv2.x, wv2.y);

            #pragma unroll
            for (int e = 0; e < 8; e++){
                int k = eb + e;
                float4 tq = *(const float4*)&s_t[k*4];   // broadcast
                ull hv = fma2(dup2(tq.z), v2, fma2(dup2(tq.y), v1, mul2(dup2(tq.x), v0)));

                float a0,a1,b0,b1;
                unpack2(hv, a0, a1);
                unpack2(hd[e], b0, b1);
                float sa0,ca0,sa1,ca1,sb0,cb0,sb1,cb1;
                __sincosf(a0,&sa0,&ca0); __sincosf(a1,&sa1,&ca1);
                __sincosf(b0,&sb0,&cb0); __sincosf(b1,&sb1,&cb1);
                size_t obase = ((size_t)(r*K_ + k))*256 + col;
                __stcs((float2*)&out[obase],       make_float2(ca0+cb0, ca1+cb1));
                __stcs((float2*)&out[obase + 128], make_float2(sa0+sb0, sa1+sb1));
            }
        }

        asm volatile("cp.async.wait_group 0;" ::: "memory");
        __syncthreads();
        if (!hn) break;
        r = rn; b ^= 1;
    }
}

// ---------------------------------------------------------------------------
extern "C" void kernel_launch(void* const* d_in, const int* in_sizes, int n_in,
                              void* d_out, int out_size){
    const float* X     = (const float*)d_in[0];
    const void*  eidx  = d_in[1];
    const void*  C     = d_in[2];
    const float* Wvec  = (const float*)d_in[3];
    const float* Wdist = (const float*)d_in[4];
    (void)in_sizes; (void)n_in; (void)out_size;

    prep_kernel<<<33, 256>>>(X, C, Wvec, Wdist);
    edge_kernel<<<GRID_, 256>>>(X, eidx, (float*)d_out);
}